// round 2
// baseline (speedup 1.0000x reference)
#include <cuda_runtime.h>
#include <math.h>

#define DIM    2048
#define HIDDEN 5324
#define BATCH  16384

// ---------------- scratch (device globals; no allocation allowed) ----------
__device__ float g_h1 [BATCH * DIM];            // h after first residual add
__device__ float g_hn1[BATCH * DIM];            // rmsnorm(h, g1)
__device__ float g_v  [BATCH * DIM];            // v projection
__device__ float g_h2 [BATCH * DIM];            // h after attn residual
__device__ float g_hn2[BATCH * DIM];            // rmsnorm(h2, g2)
__device__ float g_ffh[(size_t)BATCH * HIDDEN]; // silu(h@w1^T)*(h@w2^T)

// ---------------- fused (optional add) + rmsnorm ---------------------------
// one block per row; 256 threads; 2048 floats/row = 2 float4 per thread
template <bool ADD>
__global__ void __launch_bounds__(256) rmsnorm_kernel(
    const float* __restrict__ a, const float* __restrict__ b,
    const float* __restrict__ g,
    float* __restrict__ h_out, float* __restrict__ hn_out)
{
    const int row = blockIdx.x;
    const size_t base = (size_t)row * DIM;
    const float4* a4 = (const float4*)(a + base);
    const float4* b4 = ADD ? (const float4*)(b + base) : nullptr;
    const float4* g4 = (const float4*)g;

    float4 v[2];
    float ss = 0.f;
#pragma unroll
    for (int i = 0; i < 2; i++) {
        int idx = threadIdx.x + i * 256;
        float4 x = a4[idx];
        if (ADD) {
            float4 y = b4[idx];
            x.x += y.x; x.y += y.y; x.z += y.z; x.w += y.w;
        }
        v[i] = x;
        ss += x.x * x.x + x.y * x.y + x.z * x.z + x.w * x.w;
    }

    // block reduction
    __shared__ float red[8];
#pragma unroll
    for (int o = 16; o; o >>= 1) ss += __shfl_xor_sync(0xffffffffu, ss, o);
    if ((threadIdx.x & 31) == 0) red[threadIdx.x >> 5] = ss;
    __syncthreads();
    float tot = red[0] + red[1] + red[2] + red[3] + red[4] + red[5] + red[6] + red[7];

    const float norm = sqrtf(tot);
    const float inv  = 0.022097086912079613f / fmaxf(norm, 1e-12f); // DIM^-0.5 / max(norm,eps)

    float4* h4  = ADD ? (float4*)(h_out + base) : nullptr;
    float4* hn4 = (float4*)(hn_out + base);
#pragma unroll
    for (int i = 0; i < 2; i++) {
        int idx = threadIdx.x + i * 256;
        float4 x = v[i];
        if (ADD) h4[idx] = x;
        float4 gg = g4[idx];
        float4 o;
        o.x = x.x * inv * gg.x; o.y = x.y * inv * gg.y;
        o.z = x.z * inv * gg.z; o.w = x.w * inv * gg.w;
        hn4[idx] = o;
    }
}

// ---------------- generic NT GEMM: C[M,N] = A[M,K] * B[N,K]^T (+bias)(+res)
// 128x128 tile, BK=16, 256 threads, 8x8 per thread
template <bool HAS_BIAS, bool HAS_RES>
__global__ void __launch_bounds__(256, 2) gemm_nt(
    const float* __restrict__ A, const float* __restrict__ B,
    const float* __restrict__ bias, const float* __restrict__ res,
    float* __restrict__ C, int M, int N, int K)
{
    const int BM = 128, BN = 128, BK = 16;
    __shared__ float As[BK][BM];
    __shared__ float Bs[BK][BN];

    const int tid = threadIdx.x;
    const int tx = tid & 15;        // N direction (8 cols each)
    const int ty = tid >> 4;        // M direction (8 rows each)
    const int m0 = blockIdx.y * BM;
    const int n0 = blockIdx.x * BN;

    float acc[8][8] = {};

    for (int k0 = 0; k0 < K; k0 += BK) {
        // load A tile: 128 rows x 16 cols = 512 float4, 2 per thread
#pragma unroll
        for (int t = 0; t < 2; t++) {
            int f  = tid + t * 256;
            int r  = f >> 2, c4 = f & 3;
            int kk = k0 + c4 * 4;
            float4 v = make_float4(0.f, 0.f, 0.f, 0.f);
            if (kk < K)                       // K is a multiple of 4
                v = *(const float4*)&A[(size_t)(m0 + r) * K + kk];
            As[c4 * 4 + 0][r] = v.x; As[c4 * 4 + 1][r] = v.y;
            As[c4 * 4 + 2][r] = v.z; As[c4 * 4 + 3][r] = v.w;
        }
        // load B tile
#pragma unroll
        for (int t = 0; t < 2; t++) {
            int f  = tid + t * 256;
            int r  = f >> 2, c4 = f & 3;
            int kk = k0 + c4 * 4;
            float4 v = make_float4(0.f, 0.f, 0.f, 0.f);
            if (kk < K && (n0 + r) < N)
                v = *(const float4*)&B[(size_t)(n0 + r) * K + kk];
            Bs[c4 * 4 + 0][r] = v.x; Bs[c4 * 4 + 1][r] = v.y;
            Bs[c4 * 4 + 2][r] = v.z; Bs[c4 * 4 + 3][r] = v.w;
        }
        __syncthreads();

#pragma unroll
        for (int k = 0; k < BK; k++) {
            float ra[8], rb[8];
#pragma unroll
            for (int i = 0; i < 8; i++) ra[i] = As[k][ty * 8 + i];
#pragma unroll
            for (int j = 0; j < 8; j++) rb[j] = Bs[k][tx * 8 + j];
#pragma unroll
            for (int i = 0; i < 8; i++)
#pragma unroll
                for (int j = 0; j < 8; j++)
                    acc[i][j] = fmaf(ra[i], rb[j], acc[i][j]);
        }
        __syncthreads();
    }

    // epilogue
#pragma unroll
    for (int i = 0; i < 8; i++) {
        int m = m0 + ty * 8 + i;
#pragma unroll
        for (int j = 0; j < 8; j++) {
            int n = n0 + tx * 8 + j;
            if (n < N) {
                float c = acc[i][j];
                if (HAS_BIAS) c += bias[n];
                if (HAS_RES)  c += res[(size_t)m * N + n];
                C[(size_t)m * N + n] = c;
            }
        }
    }
}

// ---------------- dual GEMM with silu gate: C = silu(A*B1^T) * (A*B2^T) ----
// 128x64 tile, BK=16, 256 threads, 8x4 per thread, two accumulators
__global__ void __launch_bounds__(256, 2) gemm_dual_silu(
    const float* __restrict__ A, const float* __restrict__ B1,
    const float* __restrict__ B2, float* __restrict__ C,
    int M, int N, int K)
{
    const int BM = 128, BN = 64, BK = 16;
    __shared__ float As [BK][BM];
    __shared__ float B1s[BK][BN];
    __shared__ float B2s[BK][BN];

    const int tid = threadIdx.x;
    const int tx = tid & 15;        // N direction (4 cols each)
    const int ty = tid >> 4;        // M direction (8 rows each)
    const int m0 = blockIdx.y * BM;
    const int n0 = blockIdx.x * BN;

    float acc1[8][4] = {};
    float acc2[8][4] = {};

    for (int k0 = 0; k0 < K; k0 += BK) {
        // A tile: 512 float4, 2 per thread
#pragma unroll
        for (int t = 0; t < 2; t++) {
            int f  = tid + t * 256;
            int r  = f >> 2, c4 = f & 3;
            int kk = k0 + c4 * 4;
            float4 v = make_float4(0.f, 0.f, 0.f, 0.f);
            if (kk < K)
                v = *(const float4*)&A[(size_t)(m0 + r) * K + kk];
            As[c4 * 4 + 0][r] = v.x; As[c4 * 4 + 1][r] = v.y;
            As[c4 * 4 + 2][r] = v.z; As[c4 * 4 + 3][r] = v.w;
        }
        // B1/B2 tiles: 64 rows x 16 cols = 256 float4 each, 1 per thread
        {
            int f  = tid;
            int r  = f >> 2, c4 = f & 3;
            int kk = k0 + c4 * 4;
            bool ok = (kk < K) && ((n0 + r) < N);
            float4 v1 = make_float4(0.f, 0.f, 0.f, 0.f);
            float4 v2 = make_float4(0.f, 0.f, 0.f, 0.f);
            if (ok) {
                v1 = *(const float4*)&B1[(size_t)(n0 + r) * K + kk];
                v2 = *(const float4*)&B2[(size_t)(n0 + r) * K + kk];
            }
            B1s[c4 * 4 + 0][r] = v1.x; B1s[c4 * 4 + 1][r] = v1.y;
            B1s[c4 * 4 + 2][r] = v1.z; B1s[c4 * 4 + 3][r] = v1.w;
            B2s[c4 * 4 + 0][r] = v2.x; B2s[c4 * 4 + 1][r] = v2.y;
            B2s[c4 * 4 + 2][r] = v2.z; B2s[c4 * 4 + 3][r] = v2.w;
        }
        __syncthreads();

#pragma unroll
        for (int k = 0; k < BK; k++) {
            float ra[8], rb1[4], rb2[4];
#pragma unroll
            for (int i = 0; i < 8; i++) ra[i] = As[k][ty * 8 + i];
#pragma unroll
            for (int j = 0; j < 4; j++) { rb1[j] = B1s[k][tx * 4 + j]; rb2[j] = B2s[k][tx * 4 + j]; }
#pragma unroll
            for (int i = 0; i < 8; i++)
#pragma unroll
                for (int j = 0; j < 4; j++) {
                    acc1[i][j] = fmaf(ra[i], rb1[j], acc1[i][j]);
                    acc2[i][j] = fmaf(ra[i], rb2[j], acc2[i][j]);
                }
        }
        __syncthreads();
    }

#pragma unroll
    for (int i = 0; i < 8; i++) {
        int m = m0 + ty * 8 + i;
#pragma unroll
        for (int j = 0; j < 4; j++) {
            int n = n0 + tx * 4 + j;
            if (n < N) {
                float u = acc1[i][j];
                float s = u / (1.f + expf(-u));   // silu
                C[(size_t)m * N + n] = s * acc2[i][j];
            }
        }
    }
}

// ---------------- launch ---------------------------------------------------
extern "C" void kernel_launch(void* const* d_in, const int* in_sizes, int n_in,
                              void* d_out, int out_size)
{
    const float* x          = (const float*)d_in[0];
    const float* state      = (const float*)d_in[1];
    const float* g1         = (const float*)d_in[2];
    const float* g2         = (const float*)d_in[3];
    const float* in_proj_w  = (const float*)d_in[4];
    const float* in_proj_b  = (const float*)d_in[5];
    const float* out_proj_w = (const float*)d_in[6];
    const float* out_proj_b = (const float*)d_in[7];
    const float* w1         = (const float*)d_in[8];
    const float* w2         = (const float*)d_in[9];
    const float* w3         = (const float*)d_in[10];
    float* out = (float*)d_out;

    const float* wv = in_proj_w + (size_t)2 * DIM * DIM;  // only V slice is live
    const float* bv = in_proj_b + 2 * DIM;

    float *h1, *hn1, *v, *h2, *hn2, *ffh;
    cudaGetSymbolAddress((void**)&h1,  g_h1);
    cudaGetSymbolAddress((void**)&hn1, g_hn1);
    cudaGetSymbolAddress((void**)&v,   g_v);
    cudaGetSymbolAddress((void**)&h2,  g_h2);
    cudaGetSymbolAddress((void**)&hn2, g_hn2);
    cudaGetSymbolAddress((void**)&ffh, g_ffh);

    // 1. h1 = x + state ; hn1 = rmsnorm(h1, g1)
    rmsnorm_kernel<true><<<BATCH, 256>>>(x, state, g1, h1, hn1);

    // 2. v = hn1 @ wv^T + bv
    gemm_nt<true, false><<<dim3(DIM / 128, BATCH / 128), 256>>>(
        hn1, wv, bv, nullptr, v, BATCH, DIM, DIM);

    // 3. h2 = h1 + v @ out_proj_w^T + out_proj_b
    gemm_nt<true, true><<<dim3(DIM / 128, BATCH / 128), 256>>>(
        v, out_proj_w, out_proj_b, h1, h2, BATCH, DIM, DIM);

    // 4. hn2 = rmsnorm(h2, g2)
    rmsnorm_kernel<false><<<BATCH, 256>>>(h2, nullptr, g2, nullptr, hn2);

    // 5. ffh = silu(hn2 @ w1^T) * (hn2 @ w2^T)
    gemm_dual_silu<<<dim3((HIDDEN + 63) / 64, BATCH / 128), 256>>>(
        hn2, w1, w2, ffh, BATCH, HIDDEN, DIM);

    // 6. out = h2 + ffh @ w3^T
    gemm_nt<false, true><<<dim3(DIM / 128, BATCH / 128), 256>>>(
        ffh, w3, nullptr, h2, out, BATCH, DIM, HIDDEN);
}

// round 4
// speedup vs baseline: 2.5991x; 2.5991x over previous
#include <cuda_runtime.h>
#include <cstdint>
#include <math.h>

#define DIM    2048
#define HIDDEN 5324
#define BATCH  16384

// ---------------- scratch (device globals; no allocation allowed) ----------
__device__ float g_h1 [BATCH * DIM];
__device__ float g_hn1[BATCH * DIM];
__device__ float g_v  [BATCH * DIM];
__device__ float g_h2 [BATCH * DIM];
__device__ float g_hn2[BATCH * DIM];
__device__ float g_ffh[(size_t)BATCH * HIDDEN];

// ---------------- PTX helpers ----------------------------------------------
__device__ __forceinline__ uint32_t smem_u32(const void* p) {
    uint32_t a;
    asm("{ .reg .u64 t; cvta.to.shared.u64 t, %1; cvt.u32.u64 %0, t; }"
        : "=r"(a) : "l"(p));
    return a;
}
__device__ __forceinline__ void cp16(uint32_t dst, const void* src, uint32_t sz) {
    asm volatile("cp.async.cg.shared.global [%0], [%1], 16, %2;"
                 :: "r"(dst), "l"(src), "r"(sz));
}
#define CP_COMMIT()  asm volatile("cp.async.commit_group;" ::: "memory")
#define CP_WAIT1()   asm volatile("cp.async.wait_group 1;" ::: "memory")

// m16n8k4 tf32 HMMA: D += A*B.  a0=(g,t) a1=(g+8,t)  b0=(t,g)
// c0=(g,2t) c1=(g,2t+1) c2=(g+8,2t) c3=(g+8,2t+1)
__device__ __forceinline__ void mma4(float* c, uint32_t a0, uint32_t a1, uint32_t b0) {
    asm volatile(
        "mma.sync.aligned.m16n8k4.row.col.f32.tf32.tf32.f32 "
        "{%0,%1,%2,%3}, {%4,%5}, {%6}, {%0,%1,%2,%3};"
        : "+f"(c[0]), "+f"(c[1]), "+f"(c[2]), "+f"(c[3])
        : "r"(a0), "r"(a1), "r"(b0));
}

// ---------------- fused (optional add) + rmsnorm ---------------------------
template <bool ADD>
__global__ void __launch_bounds__(256) rmsnorm_kernel(
    const float* __restrict__ a, const float* __restrict__ b,
    const float* __restrict__ g,
    float* __restrict__ h_out, float* __restrict__ hn_out)
{
    const int row = blockIdx.x;
    const size_t base = (size_t)row * DIM;
    const float4* a4 = (const float4*)(a + base);
    const float4* b4 = ADD ? (const float4*)(b + base) : nullptr;
    const float4* g4 = (const float4*)g;

    float4 v[2];
    float ss = 0.f;
#pragma unroll
    for (int i = 0; i < 2; i++) {
        int idx = threadIdx.x + i * 256;
        float4 x = a4[idx];
        if (ADD) {
            float4 y = b4[idx];
            x.x += y.x; x.y += y.y; x.z += y.z; x.w += y.w;
        }
        v[i] = x;
        ss += x.x * x.x + x.y * x.y + x.z * x.z + x.w * x.w;
    }
    __shared__ float red[8];
#pragma unroll
    for (int o = 16; o; o >>= 1) ss += __shfl_xor_sync(0xffffffffu, ss, o);
    if ((threadIdx.x & 31) == 0) red[threadIdx.x >> 5] = ss;
    __syncthreads();
    float tot = red[0] + red[1] + red[2] + red[3] + red[4] + red[5] + red[6] + red[7];

    const float norm = sqrtf(tot);
    const float inv  = 0.022097086912079613f / fmaxf(norm, 1e-12f);

    float4* h4  = ADD ? (float4*)(h_out + base) : nullptr;
    float4* hn4 = (float4*)(hn_out + base);
#pragma unroll
    for (int i = 0; i < 2; i++) {
        int idx = threadIdx.x + i * 256;
        float4 x = v[i];
        if (ADD) h4[idx] = x;
        float4 gg = g4[idx];
        float4 o;
        o.x = x.x * inv * gg.x; o.y = x.y * inv * gg.y;
        o.z = x.z * inv * gg.z; o.w = x.w * inv * gg.w;
        hn4[idx] = o;
    }
}

// ---------------- tf32 HMMA GEMM: C[M,N] = A[M,K] @ B[N,K]^T (+bias)(+res) -
// CTA 128x128, BK=32, 4 warps (2x2), warp tile 64x64.
// smem: per stage A[128][36] + B[128][36] floats (row stride 36 = 144B,
// conflict-free 4q+t bank pattern, 16B-aligned for cp.async). 2 stages.
// Requires N % 128 == 0 (true for all uses: N = 2048).  K % 4 == 0.
template <bool BIAS, bool RES>
__global__ void __launch_bounds__(128, 2) gemm_tc(
    const float* __restrict__ A, const float* __restrict__ B,
    const float* __restrict__ bias, const float* __restrict__ res,
    float* __restrict__ C, int M, int N, int K)
{
    extern __shared__ float sm[];
    const int tid = threadIdx.x, wid = tid >> 5, lid = tid & 31;
    const int q = lid >> 2, t = lid & 3;
    const int m0 = blockIdx.y * 128, n0 = blockIdx.x * 128;
    const int wm = (wid >> 1) * 64, wn = (wid & 1) * 64;
    const int KT = (K + 31) >> 5;
    const uint32_t sbase = smem_u32(sm);

    auto load = [&](int kc_, int s) {
        const int k0 = kc_ << 5;
        const uint32_t as = sbase + s * 36864u;
        const uint32_t bs = as + 18432u;
#pragma unroll
        for (int i = 0; i < 8; i++) {
            int idx = tid + i * 128;
            int r = idx >> 3, c = idx & 7;
            int kk = k0 + c * 4;
            uint32_t ok = (kk < K) ? 16u : 0u;
            cp16(as + (uint32_t)(r * 144 + c * 16),
                 A + (size_t)(m0 + r) * K + (ok ? kk : 0), ok);
        }
#pragma unroll
        for (int i = 0; i < 8; i++) {
            int idx = tid + i * 128;
            int r = idx >> 3, c = idx & 7;
            int kk = k0 + c * 4;
            uint32_t ok = (kk < K) ? 16u : 0u;
            cp16(bs + (uint32_t)(r * 144 + c * 16),
                 B + (size_t)(n0 + r) * K + (ok ? kk : 0), ok);
        }
        CP_COMMIT();
    };

    float acc[4][8][4] = {};
    load(0, 0);
    load(1, 1);

    for (int kc = 0; kc < KT; kc++) {
        const int s = kc & 1;
        CP_WAIT1();
        __syncthreads();
        const float* As = sm + s * 9216;
        const float* Bs = As + 4608;
        const float* ap = As + (wm + q) * 36 + t;
        const float* bp = Bs + (wn + q) * 36 + t;
#pragma unroll
        for (int ks = 0; ks < 8; ks++) {
            uint32_t af[4][2], bf[8];
#pragma unroll
            for (int mt = 0; mt < 4; mt++) {
                af[mt][0] = __float_as_uint(ap[(mt * 16)     * 36 + ks * 4]);
                af[mt][1] = __float_as_uint(ap[(mt * 16 + 8) * 36 + ks * 4]);
            }
#pragma unroll
            for (int nt = 0; nt < 8; nt++)
                bf[nt] = __float_as_uint(bp[nt * 8 * 36 + ks * 4]);
#pragma unroll
            for (int mt = 0; mt < 4; mt++)
#pragma unroll
                for (int nt = 0; nt < 8; nt++)
                    mma4(acc[mt][nt], af[mt][0], af[mt][1], bf[nt]);
        }
        __syncthreads();
        if (kc + 2 < KT) load(kc + 2, s);
        else             CP_COMMIT();
    }

    // epilogue
#pragma unroll
    for (int mt = 0; mt < 4; mt++) {
#pragma unroll
        for (int half = 0; half < 2; half++) {
            const int r = m0 + wm + mt * 16 + q + half * 8;
            float*       Crow = C + (size_t)r * N;
            const float* Rrow = RES ? res + (size_t)r * N : nullptr;
#pragma unroll
            for (int nt = 0; nt < 8; nt++) {
                int n = n0 + wn + nt * 8 + 2 * t;
                float2 v;
                v.x = acc[mt][nt][half * 2 + 0];
                v.y = acc[mt][nt][half * 2 + 1];
                if (BIAS) { float2 b = *(const float2*)&bias[n]; v.x += b.x; v.y += b.y; }
                if (RES)  { float2 rr = *(const float2*)&Rrow[n]; v.x += rr.x; v.y += rr.y; }
                *(float2*)&Crow[n] = v;
            }
        }
    }
}

// ---------------- tf32 HMMA dual GEMM: C = silu(A@B1^T) * (A@B2^T) ---------
// CTA 128x64 (per B), BK=32, 4 warps (2x2), warp tile 64x32 per matrix.
__global__ void __launch_bounds__(128, 2) gemm_dual_tc(
    const float* __restrict__ A, const float* __restrict__ B1,
    const float* __restrict__ B2, float* __restrict__ C,
    int M, int N, int K)
{
    extern __shared__ float sm[];
    const int tid = threadIdx.x, wid = tid >> 5, lid = tid & 31;
    const int q = lid >> 2, t = lid & 3;
    const int m0 = blockIdx.y * 128, n0 = blockIdx.x * 64;
    const int wm = (wid >> 1) * 64, wn = (wid & 1) * 32;
    const int KT = (K + 31) >> 5;
    const uint32_t sbase = smem_u32(sm);

    auto load = [&](int kc_, int s) {
        const int k0 = kc_ << 5;
        const uint32_t as  = sbase + s * 36864u;
        const uint32_t b1s = as + 18432u;
        const uint32_t b2s = as + 27648u;
#pragma unroll
        for (int i = 0; i < 8; i++) {
            int idx = tid + i * 128;
            int r = idx >> 3, c = idx & 7;
            int kk = k0 + c * 4;
            uint32_t ok = (kk < K) ? 16u : 0u;
            cp16(as + (uint32_t)(r * 144 + c * 16),
                 A + (size_t)(m0 + r) * K + (ok ? kk : 0), ok);
        }
#pragma unroll
        for (int i = 0; i < 4; i++) {
            int idx = tid + i * 128;
            int r = idx >> 3, c = idx & 7;
            int kk = k0 + c * 4;
            uint32_t ok = ((kk < K) && (n0 + r < N)) ? 16u : 0u;
            size_t off = ok ? ((size_t)(n0 + r) * K + kk) : 0;
            uint32_t sw = (uint32_t)(r * 144 + c * 16);
            cp16(b1s + sw, B1 + off, ok);
            cp16(b2s + sw, B2 + off, ok);
        }
        CP_COMMIT();
    };

    float acc1[4][4][4] = {};
    float acc2[4][4][4] = {};
    load(0, 0);
    load(1, 1);

    for (int kc = 0; kc < KT; kc++) {
        const int s = kc & 1;
        CP_WAIT1();
        __syncthreads();
        const float* As  = sm + s * 9216;
        const float* B1s = As + 4608;
        const float* B2s = As + 6912;
        const float* ap  = As  + (wm + q) * 36 + t;
        const float* b1p = B1s + (wn + q) * 36 + t;
        const float* b2p = B2s + (wn + q) * 36 + t;
#pragma unroll
        for (int ks = 0; ks < 8; ks++) {
            uint32_t af[4][2], b1f[4], b2f[4];
#pragma unroll
            for (int mt = 0; mt < 4; mt++) {
                af[mt][0] = __float_as_uint(ap[(mt * 16)     * 36 + ks * 4]);
                af[mt][1] = __float_as_uint(ap[(mt * 16 + 8) * 36 + ks * 4]);
            }
#pragma unroll
            for (int nt = 0; nt < 4; nt++) {
                b1f[nt] = __float_as_uint(b1p[nt * 8 * 36 + ks * 4]);
                b2f[nt] = __float_as_uint(b2p[nt * 8 * 36 + ks * 4]);
            }
#pragma unroll
            for (int mt = 0; mt < 4; mt++)
#pragma unroll
                for (int nt = 0; nt < 4; nt++) {
                    mma4(acc1[mt][nt], af[mt][0], af[mt][1], b1f[nt]);
                    mma4(acc2[mt][nt], af[mt][0], af[mt][1], b2f[nt]);
                }
        }
        __syncthreads();
        if (kc + 2 < KT) load(kc + 2, s);
        else             CP_COMMIT();
    }

    // epilogue: silu(acc1) * acc2
#pragma unroll
    for (int mt = 0; mt < 4; mt++) {
#pragma unroll
        for (int half = 0; half < 2; half++) {
            const int r = m0 + wm + mt * 16 + q + half * 8;
            float* Crow = C + (size_t)r * N;
#pragma unroll
            for (int nt = 0; nt < 4; nt++) {
                int n = n0 + wn + nt * 8 + 2 * t;
                if (n < N) {
                    float u0 = acc1[mt][nt][half * 2 + 0];
                    float u1 = acc1[mt][nt][half * 2 + 1];
                    float2 v;
                    v.x = u0 / (1.f + expf(-u0)) * acc2[mt][nt][half * 2 + 0];
                    v.y = u1 / (1.f + expf(-u1)) * acc2[mt][nt][half * 2 + 1];
                    *(float2*)&Crow[n] = v;
                }
            }
        }
    }
}

// ---------------- launch ---------------------------------------------------
extern "C" void kernel_launch(void* const* d_in, const int* in_sizes, int n_in,
                              void* d_out, int out_size)
{
    const float* x          = (const float*)d_in[0];
    const float* state      = (const float*)d_in[1];
    const float* g1         = (const float*)d_in[2];
    const float* g2         = (const float*)d_in[3];
    const float* in_proj_w  = (const float*)d_in[4];
    const float* in_proj_b  = (const float*)d_in[5];
    const float* out_proj_w = (const float*)d_in[6];
    const float* out_proj_b = (const float*)d_in[7];
    const float* w1         = (const float*)d_in[8];
    const float* w2         = (const float*)d_in[9];
    const float* w3         = (const float*)d_in[10];
    float* out = (float*)d_out;

    const float* wv = in_proj_w + (size_t)2 * DIM * DIM;   // only V slice is live
    const float* bv = in_proj_b + 2 * DIM;

    float *h1, *hn1, *v, *h2, *hn2, *ffh;
    cudaGetSymbolAddress((void**)&h1,  g_h1);
    cudaGetSymbolAddress((void**)&hn1, g_hn1);
    cudaGetSymbolAddress((void**)&v,   g_v);
    cudaGetSymbolAddress((void**)&h2,  g_h2);
    cudaGetSymbolAddress((void**)&hn2, g_hn2);
    cudaGetSymbolAddress((void**)&ffh, g_ffh);

    const int SMEM = 73728;   // 2 stages x 36864 B
    cudaFuncSetAttribute(gemm_tc<true,  false>, cudaFuncAttributeMaxDynamicSharedMemorySize, SMEM);
    cudaFuncSetAttribute(gemm_tc<true,  true >, cudaFuncAttributeMaxDynamicSharedMemorySize, SMEM);
    cudaFuncSetAttribute(gemm_tc<false, true >, cudaFuncAttributeMaxDynamicSharedMemorySize, SMEM);
    cudaFuncSetAttribute(gemm_dual_tc,          cudaFuncAttributeMaxDynamicSharedMemorySize, SMEM);

    // 1. h1 = x + state ; hn1 = rmsnorm(h1, g1)
    rmsnorm_kernel<true><<<BATCH, 256>>>(x, state, g1, h1, hn1);

    // 2. v = hn1 @ wv^T + bv
    gemm_tc<true, false><<<dim3(DIM / 128, BATCH / 128), 128, SMEM>>>(
        hn1, wv, bv, nullptr, v, BATCH, DIM, DIM);

    // 3. h2 = h1 + v @ out_proj_w^T + out_proj_b
    gemm_tc<true, true><<<dim3(DIM / 128, BATCH / 128), 128, SMEM>>>(
        v, out_proj_w, out_proj_b, h1, h2, BATCH, DIM, DIM);

    // 4. hn2 = rmsnorm(h2, g2)
    rmsnorm_kernel<false><<<BATCH, 256>>>(h2, nullptr, g2, nullptr, hn2);

    // 5. ffh = silu(hn2 @ w1^T) * (hn2 @ w2^T)
    gemm_dual_tc<<<dim3((HIDDEN + 63) / 64, BATCH / 128), 128, SMEM>>>(
        hn2, w1, w2, ffh, BATCH, HIDDEN, DIM);

    // 6. out = h2 + ffh @ w3^T
    gemm_tc<false, true><<<dim3(DIM / 128, BATCH / 128), 128, SMEM>>>(
        ffh, w3, nullptr, h2, out, BATCH, DIM, HIDDEN);
}

// round 5
// speedup vs baseline: 3.9518x; 1.5205x over previous
#include <cuda_runtime.h>
#include <cstdint>
#include <math.h>

#define DIM    2048
#define HIDDEN 5324
#define BATCH  16384

// ---------------- scratch (device globals; no allocation allowed) ----------
__device__ float g_h1 [BATCH * DIM];
__device__ float g_hn1[BATCH * DIM];
__device__ float g_v  [BATCH * DIM];
__device__ float g_h2 [BATCH * DIM];
__device__ float g_hn2[BATCH * DIM];
__device__ float g_ffh[(size_t)BATCH * HIDDEN];

// ---------------- PTX helpers ----------------------------------------------
__device__ __forceinline__ uint32_t smem_u32(const void* p) {
    uint32_t a;
    asm("{ .reg .u64 t; cvta.to.shared.u64 t, %1; cvt.u32.u64 %0, t; }"
        : "=r"(a) : "l"(p));
    return a;
}
__device__ __forceinline__ void cp16(uint32_t dst, const void* src, uint32_t sz) {
    asm volatile("cp.async.cg.shared.global [%0], [%1], 16, %2;"
                 :: "r"(dst), "l"(src), "r"(sz));
}
#define CP_COMMIT()  asm volatile("cp.async.commit_group;" ::: "memory")
#define CP_WAIT1()   asm volatile("cp.async.wait_group 1;" ::: "memory")

// m16n8k8 tf32 HMMA (full-rate shape): D += A*B
// A: a0=(g,t) a1=(g+8,t) a2=(g,t+4) a3=(g+8,t+4)   [row=m, col=k]
// B: b0=(t,g) b1=(t+4,g)                            [row=k, col=n]
// C: c0=(g,2t) c1=(g,2t+1) c2=(g+8,2t) c3=(g+8,2t+1)
__device__ __forceinline__ void mma8(float* c, const uint32_t* a, const uint32_t* b) {
    asm volatile(
        "mma.sync.aligned.m16n8k8.row.col.f32.tf32.tf32.f32 "
        "{%0,%1,%2,%3}, {%4,%5,%6,%7}, {%8,%9}, {%0,%1,%2,%3};"
        : "+f"(c[0]), "+f"(c[1]), "+f"(c[2]), "+f"(c[3])
        : "r"(a[0]), "r"(a[1]), "r"(a[2]), "r"(a[3]), "r"(b[0]), "r"(b[1]));
}

// ---------------- fused (optional add) + rmsnorm ---------------------------
template <bool ADD>
__global__ void __launch_bounds__(256) rmsnorm_kernel(
    const float* __restrict__ a, const float* __restrict__ b,
    const float* __restrict__ g,
    float* __restrict__ h_out, float* __restrict__ hn_out)
{
    const int row = blockIdx.x;
    const size_t base = (size_t)row * DIM;
    const float4* a4 = (const float4*)(a + base);
    const float4* b4 = ADD ? (const float4*)(b + base) : nullptr;
    const float4* g4 = (const float4*)g;

    float4 v[2];
    float ss = 0.f;
#pragma unroll
    for (int i = 0; i < 2; i++) {
        int idx = threadIdx.x + i * 256;
        float4 x = a4[idx];
        if (ADD) {
            float4 y = b4[idx];
            x.x += y.x; x.y += y.y; x.z += y.z; x.w += y.w;
        }
        v[i] = x;
        ss += x.x * x.x + x.y * x.y + x.z * x.z + x.w * x.w;
    }
    __shared__ float red[8];
#pragma unroll
    for (int o = 16; o; o >>= 1) ss += __shfl_xor_sync(0xffffffffu, ss, o);
    if ((threadIdx.x & 31) == 0) red[threadIdx.x >> 5] = ss;
    __syncthreads();
    float tot = red[0] + red[1] + red[2] + red[3] + red[4] + red[5] + red[6] + red[7];

    const float norm = sqrtf(tot);
    const float inv  = 0.022097086912079613f / fmaxf(norm, 1e-12f);

    float4* h4  = ADD ? (float4*)(h_out + base) : nullptr;
    float4* hn4 = (float4*)(hn_out + base);
#pragma unroll
    for (int i = 0; i < 2; i++) {
        int idx = threadIdx.x + i * 256;
        float4 x = v[i];
        if (ADD) h4[idx] = x;
        float4 gg = g4[idx];
        float4 o;
        o.x = x.x * inv * gg.x; o.y = x.y * inv * gg.y;
        o.z = x.z * inv * gg.z; o.w = x.w * inv * gg.w;
        hn4[idx] = o;
    }
}

// ---------------- tf32 HMMA GEMM: C[M,N] = A[M,K] @ B[N,K]^T (+bias)(+res) -
// CTA 128x128, BK=32, 4 warps (2x2), warp tile 64x64, m16n8k8.
// smem: per stage A[128][36] + B[128][36] floats. 2 stages.
template <bool BIAS, bool RES>
__global__ void __launch_bounds__(128, 2) gemm_tc(
    const float* __restrict__ A, const float* __restrict__ B,
    const float* __restrict__ bias, const float* __restrict__ res,
    float* __restrict__ C, int M, int N, int K)
{
    extern __shared__ float sm[];
    const int tid = threadIdx.x, wid = tid >> 5, lid = tid & 31;
    const int q = lid >> 2, t = lid & 3;
    const int m0 = blockIdx.y * 128, n0 = blockIdx.x * 128;
    const int wm = (wid >> 1) * 64, wn = (wid & 1) * 64;
    const int KT = (K + 31) >> 5;
    const uint32_t sbase = smem_u32(sm);

    auto load = [&](int kc_, int s) {
        const int k0 = kc_ << 5;
        const uint32_t as = sbase + s * 36864u;
        const uint32_t bs = as + 18432u;
#pragma unroll
        for (int i = 0; i < 8; i++) {
            int idx = tid + i * 128;
            int r = idx >> 3, c = idx & 7;
            int kk = k0 + c * 4;
            uint32_t ok = (kk < K) ? 16u : 0u;
            cp16(as + (uint32_t)(r * 144 + c * 16),
                 A + (size_t)(m0 + r) * K + (ok ? kk : 0), ok);
        }
#pragma unroll
        for (int i = 0; i < 8; i++) {
            int idx = tid + i * 128;
            int r = idx >> 3, c = idx & 7;
            int kk = k0 + c * 4;
            uint32_t ok = (kk < K) ? 16u : 0u;
            cp16(bs + (uint32_t)(r * 144 + c * 16),
                 B + (size_t)(n0 + r) * K + (ok ? kk : 0), ok);
        }
        CP_COMMIT();
    };

    float acc[4][8][4] = {};
    load(0, 0);
    load(1, 1);

    for (int kc = 0; kc < KT; kc++) {
        const int s = kc & 1;
        CP_WAIT1();
        __syncthreads();
        const float* As = sm + s * 9216;
        const float* Bs = As + 4608;
        const float* ap = As + (wm + q) * 36 + t;
        const float* bp = Bs + (wn + q) * 36 + t;
#pragma unroll
        for (int ks = 0; ks < 4; ks++) {            // 4 steps of k8
            uint32_t af[4][4], bf[8][2];
#pragma unroll
            for (int mt = 0; mt < 4; mt++) {
                af[mt][0] = __float_as_uint(ap[(mt * 16)     * 36 + ks * 8]);
                af[mt][1] = __float_as_uint(ap[(mt * 16 + 8) * 36 + ks * 8]);
                af[mt][2] = __float_as_uint(ap[(mt * 16)     * 36 + ks * 8 + 4]);
                af[mt][3] = __float_as_uint(ap[(mt * 16 + 8) * 36 + ks * 8 + 4]);
            }
#pragma unroll
            for (int nt = 0; nt < 8; nt++) {
                bf[nt][0] = __float_as_uint(bp[nt * 8 * 36 + ks * 8]);
                bf[nt][1] = __float_as_uint(bp[nt * 8 * 36 + ks * 8 + 4]);
            }
#pragma unroll
            for (int mt = 0; mt < 4; mt++)
#pragma unroll
                for (int nt = 0; nt < 8; nt++)
                    mma8(acc[mt][nt], af[mt], bf[nt]);
        }
        __syncthreads();
        if (kc + 2 < KT) load(kc + 2, s);
        else             CP_COMMIT();
    }

    // epilogue
#pragma unroll
    for (int mt = 0; mt < 4; mt++) {
#pragma unroll
        for (int half = 0; half < 2; half++) {
            const int r = m0 + wm + mt * 16 + q + half * 8;
            float*       Crow = C + (size_t)r * N;
            const float* Rrow = RES ? res + (size_t)r * N : nullptr;
#pragma unroll
            for (int nt = 0; nt < 8; nt++) {
                int n = n0 + wn + nt * 8 + 2 * t;
                float2 v;
                v.x = acc[mt][nt][half * 2 + 0];
                v.y = acc[mt][nt][half * 2 + 1];
                if (BIAS) { float2 b = *(const float2*)&bias[n]; v.x += b.x; v.y += b.y; }
                if (RES)  { float2 rr = *(const float2*)&Rrow[n]; v.x += rr.x; v.y += rr.y; }
                *(float2*)&Crow[n] = v;
            }
        }
    }
}

// ---------------- tf32 HMMA dual GEMM: C = silu(A@B1^T) * (A@B2^T) ---------
// CTA 128x64 (per B), BK=32, 4 warps (2x2), warp tile 64x32 per matrix, m16n8k8.
__global__ void __launch_bounds__(128, 2) gemm_dual_tc(
    const float* __restrict__ A, const float* __restrict__ B1,
    const float* __restrict__ B2, float* __restrict__ C,
    int M, int N, int K)
{
    extern __shared__ float sm[];
    const int tid = threadIdx.x, wid = tid >> 5, lid = tid & 31;
    const int q = lid >> 2, t = lid & 3;
    const int m0 = blockIdx.y * 128, n0 = blockIdx.x * 64;
    const int wm = (wid >> 1) * 64, wn = (wid & 1) * 32;
    const int KT = (K + 31) >> 5;
    const uint32_t sbase = smem_u32(sm);

    auto load = [&](int kc_, int s) {
        const int k0 = kc_ << 5;
        const uint32_t as  = sbase + s * 36864u;
        const uint32_t b1s = as + 18432u;
        const uint32_t b2s = as + 27648u;
#pragma unroll
        for (int i = 0; i < 8; i++) {
            int idx = tid + i * 128;
            int r = idx >> 3, c = idx & 7;
            int kk = k0 + c * 4;
            uint32_t ok = (kk < K) ? 16u : 0u;
            cp16(as + (uint32_t)(r * 144 + c * 16),
                 A + (size_t)(m0 + r) * K + (ok ? kk : 0), ok);
        }
#pragma unroll
        for (int i = 0; i < 4; i++) {
            int idx = tid + i * 128;
            int r = idx >> 3, c = idx & 7;
            int kk = k0 + c * 4;
            uint32_t ok = ((kk < K) && (n0 + r < N)) ? 16u : 0u;
            size_t off = ok ? ((size_t)(n0 + r) * K + kk) : 0;
            uint32_t sw = (uint32_t)(r * 144 + c * 16);
            cp16(b1s + sw, B1 + off, ok);
            cp16(b2s + sw, B2 + off, ok);
        }
        CP_COMMIT();
    };

    float acc1[4][4][4] = {};
    float acc2[4][4][4] = {};
    load(0, 0);
    load(1, 1);

    for (int kc = 0; kc < KT; kc++) {
        const int s = kc & 1;
        CP_WAIT1();
        __syncthreads();
        const float* As  = sm + s * 9216;
        const float* B1s = As + 4608;
        const float* B2s = As + 6912;
        const float* ap  = As  + (wm + q) * 36 + t;
        const float* b1p = B1s + (wn + q) * 36 + t;
        const float* b2p = B2s + (wn + q) * 36 + t;
#pragma unroll
        for (int ks = 0; ks < 4; ks++) {
            uint32_t af[4][4], b1f[4][2], b2f[4][2];
#pragma unroll
            for (int mt = 0; mt < 4; mt++) {
                af[mt][0] = __float_as_uint(ap[(mt * 16)     * 36 + ks * 8]);
                af[mt][1] = __float_as_uint(ap[(mt * 16 + 8) * 36 + ks * 8]);
                af[mt][2] = __float_as_uint(ap[(mt * 16)     * 36 + ks * 8 + 4]);
                af[mt][3] = __float_as_uint(ap[(mt * 16 + 8) * 36 + ks * 8 + 4]);
            }
#pragma unroll
            for (int nt = 0; nt < 4; nt++) {
                b1f[nt][0] = __float_as_uint(b1p[nt * 8 * 36 + ks * 8]);
                b1f[nt][1] = __float_as_uint(b1p[nt * 8 * 36 + ks * 8 + 4]);
                b2f[nt][0] = __float_as_uint(b2p[nt * 8 * 36 + ks * 8]);
                b2f[nt][1] = __float_as_uint(b2p[nt * 8 * 36 + ks * 8 + 4]);
            }
#pragma unroll
            for (int mt = 0; mt < 4; mt++)
#pragma unroll
                for (int nt = 0; nt < 4; nt++) {
                    mma8(acc1[mt][nt], af[mt], b1f[nt]);
                    mma8(acc2[mt][nt], af[mt], b2f[nt]);
                }
        }
        __syncthreads();
        if (kc + 2 < KT) load(kc + 2, s);
        else             CP_COMMIT();
    }

    // epilogue: silu(acc1) * acc2
#pragma unroll
    for (int mt = 0; mt < 4; mt++) {
#pragma unroll
        for (int half = 0; half < 2; half++) {
            const int r = m0 + wm + mt * 16 + q + half * 8;
            float* Crow = C + (size_t)r * N;
#pragma unroll
            for (int nt = 0; nt < 4; nt++) {
                int n = n0 + wn + nt * 8 + 2 * t;
                if (n < N) {
                    float u0 = acc1[mt][nt][half * 2 + 0];
                    float u1 = acc1[mt][nt][half * 2 + 1];
                    float2 v;
                    v.x = u0 / (1.f + expf(-u0)) * acc2[mt][nt][half * 2 + 0];
                    v.y = u1 / (1.f + expf(-u1)) * acc2[mt][nt][half * 2 + 1];
                    *(float2*)&Crow[n] = v;
                }
            }
        }
    }
}

// ---------------- launch ---------------------------------------------------
extern "C" void kernel_launch(void* const* d_in, const int* in_sizes, int n_in,
                              void* d_out, int out_size)
{
    const float* x          = (const float*)d_in[0];
    const float* state      = (const float*)d_in[1];
    const float* g1         = (const float*)d_in[2];
    const float* g2         = (const float*)d_in[3];
    const float* in_proj_w  = (const float*)d_in[4];
    const float* in_proj_b  = (const float*)d_in[5];
    const float* out_proj_w = (const float*)d_in[6];
    const float* out_proj_b = (const float*)d_in[7];
    const float* w1         = (const float*)d_in[8];
    const float* w2         = (const float*)d_in[9];
    const float* w3         = (const float*)d_in[10];
    float* out = (float*)d_out;

    const float* wv = in_proj_w + (size_t)2 * DIM * DIM;   // only V slice is live
    const float* bv = in_proj_b + 2 * DIM;

    float *h1, *hn1, *v, *h2, *hn2, *ffh;
    cudaGetSymbolAddress((void**)&h1,  g_h1);
    cudaGetSymbolAddress((void**)&hn1, g_hn1);
    cudaGetSymbolAddress((void**)&v,   g_v);
    cudaGetSymbolAddress((void**)&h2,  g_h2);
    cudaGetSymbolAddress((void**)&hn2, g_hn2);
    cudaGetSymbolAddress((void**)&ffh, g_ffh);

    const int SMEM = 73728;   // 2 stages x 36864 B
    cudaFuncSetAttribute(gemm_tc<true,  false>, cudaFuncAttributeMaxDynamicSharedMemorySize, SMEM);
    cudaFuncSetAttribute(gemm_tc<true,  true >, cudaFuncAttributeMaxDynamicSharedMemorySize, SMEM);
    cudaFuncSetAttribute(gemm_tc<false, true >, cudaFuncAttributeMaxDynamicSharedMemorySize, SMEM);
    cudaFuncSetAttribute(gemm_dual_tc,          cudaFuncAttributeMaxDynamicSharedMemorySize, SMEM);

    // 1. h1 = x + state ; hn1 = rmsnorm(h1, g1)
    rmsnorm_kernel<true><<<BATCH, 256>>>(x, state, g1, h1, hn1);

    // 2. v = hn1 @ wv^T + bv
    gemm_tc<true, false><<<dim3(DIM / 128, BATCH / 128), 128, SMEM>>>(
        hn1, wv, bv, nullptr, v, BATCH, DIM, DIM);

    // 3. h2 = h1 + v @ out_proj_w^T + out_proj_b
    gemm_tc<true, true><<<dim3(DIM / 128, BATCH / 128), 128, SMEM>>>(
        v, out_proj_w, out_proj_b, h1, h2, BATCH, DIM, DIM);

    // 4. hn2 = rmsnorm(h2, g2)
    rmsnorm_kernel<false><<<BATCH, 256>>>(h2, nullptr, g2, nullptr, hn2);

    // 5. ffh = silu(hn2 @ w1^T) * (hn2 @ w2^T)
    gemm_dual_tc<<<dim3((HIDDEN + 63) / 64, BATCH / 128), 128, SMEM>>>(
        hn2, w1, w2, ffh, BATCH, HIDDEN, DIM);

    // 6. out = h2 + ffh @ w3^T
    gemm_tc<false, true><<<dim3(DIM / 128, BATCH / 128), 128, SMEM>>>(
        ffh, w3, nullptr, h2, out, BATCH, DIM, HIDDEN);
}

// round 7
// speedup vs baseline: 7.3437x; 1.8583x over previous
#include <cuda_runtime.h>
#include <cuda_fp16.h>
#include <cstdint>
#include <math.h>

#define DIM     2048
#define HIDDEN  5324
#define HPAD    5376      // HIDDEN padded to multiple of 64 (zero-filled)
#define BATCH   16384

// ---------------- scratch (device globals; no allocation allowed) ----------
__device__ float  g_h1 [BATCH * DIM];               // fp32 residual 1
__device__ float  g_h2 [BATCH * DIM];               // fp32 residual 2
__device__ __half g_hn1[BATCH * DIM];               // rmsnorm(h1) fp16
__device__ __half g_vh [BATCH * DIM];               // v projection fp16
__device__ __half g_hn2[BATCH * DIM];               // rmsnorm(h2) fp16
__device__ __half g_ffh[(size_t)BATCH * HPAD];      // gated ffn hidden fp16
__device__ __half g_wvh [DIM * DIM];                // weight fp16 copies
__device__ __half g_owh [DIM * DIM];
__device__ __half g_w1h [(size_t)HIDDEN * DIM];
__device__ __half g_w2h [(size_t)HIDDEN * DIM];
__device__ __half g_w3h [(size_t)DIM * HPAD];       // padded, zero-filled

// ---------------- PTX helpers ----------------------------------------------
__device__ __forceinline__ uint32_t smem_u32(const void* p) {
    uint32_t a;
    asm("{ .reg .u64 t; cvta.to.shared.u64 t, %1; cvt.u32.u64 %0, t; }"
        : "=r"(a) : "l"(p));
    return a;
}
__device__ __forceinline__ void cp16(uint32_t dst, const void* src, uint32_t sz) {
    asm volatile("cp.async.cg.shared.global [%0], [%1], 16, %2;"
                 :: "r"(dst), "l"(src), "r"(sz));
}
#define CP_COMMIT()  asm volatile("cp.async.commit_group;" ::: "memory")
#define CP_WAIT1()   asm volatile("cp.async.wait_group 1;" ::: "memory")

__device__ __forceinline__ void ldm4(uint32_t* r, uint32_t addr) {
    asm volatile("ldmatrix.sync.aligned.m8n8.x4.shared.b16 {%0,%1,%2,%3}, [%4];"
                 : "=r"(r[0]), "=r"(r[1]), "=r"(r[2]), "=r"(r[3]) : "r"(addr));
}
// m16n8k16 fp16 HMMA, fp32 accumulate
__device__ __forceinline__ void mma16(float* c, const uint32_t* a, const uint32_t* b) {
    asm volatile(
        "mma.sync.aligned.m16n8k16.row.col.f32.f16.f16.f32 "
        "{%0,%1,%2,%3}, {%4,%5,%6,%7}, {%8,%9}, {%0,%1,%2,%3};"
        : "+f"(c[0]), "+f"(c[1]), "+f"(c[2]), "+f"(c[3])
        : "r"(a[0]), "r"(a[1]), "r"(a[2]), "r"(a[3]), "r"(b[0]), "r"(b[1]));
}

// ---------------- weight conversion ----------------------------------------
__global__ void __launch_bounds__(256) f2h_kernel(const float* __restrict__ s,
                                                  __half* __restrict__ d, int n4)
{
    int i = blockIdx.x * 256 + threadIdx.x;
    if (i < n4) {
        float4 v = ((const float4*)s)[i];
        __half2* o = (__half2*)d + i * 2;
        o[0] = __floats2half2_rn(v.x, v.y);
        o[1] = __floats2half2_rn(v.z, v.w);
    }
}
// rows x cols fp32 -> rows x ldd fp16 with zero pad
__global__ void __launch_bounds__(256) f2h_pad_kernel(const float* __restrict__ s,
                                                      __half* __restrict__ d,
                                                      int rows, int cols, int ldd)
{
    int i = blockIdx.x * 256 + threadIdx.x;
    int total = rows * ldd;
    if (i < total) {
        int r = i / ldd, c = i - r * ldd;
        d[i] = (c < cols) ? __float2half(s[(size_t)r * cols + c]) : __half(0.f);
    }
}

// ---------------- fused (optional add) + rmsnorm -> fp16 --------------------
template <bool ADD>
__global__ void __launch_bounds__(256) rmsnorm_kernel(
    const float* __restrict__ a, const float* __restrict__ b,
    const float* __restrict__ g,
    float* __restrict__ h_out, __half* __restrict__ hn_out)
{
    const int row = blockIdx.x;
    const size_t base = (size_t)row * DIM;
    const float4* a4 = (const float4*)(a + base);
    const float4* b4 = ADD ? (const float4*)(b + base) : nullptr;
    const float4* g4 = (const float4*)g;

    float4 v[2];
    float ss = 0.f;
#pragma unroll
    for (int i = 0; i < 2; i++) {
        int idx = threadIdx.x + i * 256;
        float4 x = a4[idx];
        if (ADD) {
            float4 y = b4[idx];
            x.x += y.x; x.y += y.y; x.z += y.z; x.w += y.w;
        }
        v[i] = x;
        ss += x.x * x.x + x.y * x.y + x.z * x.z + x.w * x.w;
    }
    __shared__ float red[8];
#pragma unroll
    for (int o = 16; o; o >>= 1) ss += __shfl_xor_sync(0xffffffffu, ss, o);
    if ((threadIdx.x & 31) == 0) red[threadIdx.x >> 5] = ss;
    __syncthreads();
    float tot = red[0] + red[1] + red[2] + red[3] + red[4] + red[5] + red[6] + red[7];

    const float norm = sqrtf(tot);
    const float inv  = 0.022097086912079613f / fmaxf(norm, 1e-12f);

    float4*  h4  = ADD ? (float4*)(h_out + base) : nullptr;
    __half2* hn2p = (__half2*)(hn_out + base);
#pragma unroll
    for (int i = 0; i < 2; i++) {
        int idx = threadIdx.x + i * 256;
        float4 x = v[i];
        if (ADD) h4[idx] = x;
        float4 gg = g4[idx];
        hn2p[idx * 2 + 0] = __floats2half2_rn(x.x * inv * gg.x, x.y * inv * gg.y);
        hn2p[idx * 2 + 1] = __floats2half2_rn(x.z * inv * gg.z, x.w * inv * gg.w);
    }
}

// ---------------- fp16 HMMA GEMM: C[M,N] = A[M,K] @ B[N,K]^T (+bias)(+res) -
// CTA 128x128, BK=64 halves, 4 warps (2x2), warp tile 64x64, m16n8k16.
// smem/stage: A[128][72] + B[128][72] halves (row stride 144B). 2 stages.
// K must be a multiple of 64 (pad with zeros). N multiple of 128.
template <bool BIAS, bool RES, bool HALF_OUT>
__global__ void __launch_bounds__(128, 2) gemm_h(
    const __half* __restrict__ A, const __half* __restrict__ B,
    const float* __restrict__ bias, const float* __restrict__ res,
    void* __restrict__ Cv, int N, int K)
{
    extern __shared__ __half sh[];
    const int tid = threadIdx.x, wid = tid >> 5, lane = tid & 31;
    const int q = lane >> 2, t = lane & 3;
    const int m0 = blockIdx.y * 128, n0 = blockIdx.x * 128;
    const int wm = (wid >> 1) * 64, wn = (wid & 1) * 64;
    const int KT = K >> 6;
    const uint32_t sbase = smem_u32(sh);

    auto load = [&](int kc_, int s) {
        const int k0 = kc_ << 6;
        const uint32_t as = sbase + s * 36864u;
        const uint32_t bs = as + 18432u;
#pragma unroll
        for (int i = 0; i < 8; i++) {           // A: 128 rows x 64 halves
            int idx = tid + i * 128;
            int r = idx >> 3, c = idx & 7;
            cp16(as + (uint32_t)(r * 144 + c * 16),
                 A + (size_t)(m0 + r) * K + k0 + c * 8, 16u);
        }
#pragma unroll
        for (int i = 0; i < 8; i++) {           // B: 128 rows x 64 halves
            int idx = tid + i * 128;
            int r = idx >> 3, c = idx & 7;
            cp16(bs + (uint32_t)(r * 144 + c * 16),
                 B + (size_t)(n0 + r) * K + k0 + c * 8, 16u);
        }
        CP_COMMIT();
    };

    float acc[4][8][4] = {};
    load(0, 0);
    load(1, 1);

    const uint32_t a_lane_off = (uint32_t)((lane & 15) * 144 + ((lane >> 4) << 4));
    const uint32_t b_lane_off = (uint32_t)(((lane & 7) + ((lane >> 4) << 3)) * 144
                                           + (((lane >> 3) & 1) << 4));

    for (int kc = 0; kc < KT; kc++) {
        const int s = kc & 1;
        CP_WAIT1();
        __syncthreads();
        const uint32_t as = sbase + s * 36864u;
        const uint32_t bs = as + 18432u;
        const uint32_t ab = as + (uint32_t)(wm * 144) + a_lane_off;
        const uint32_t bb = bs + (uint32_t)(wn * 144) + b_lane_off;
#pragma unroll
        for (int ks = 0; ks < 4; ks++) {        // 4 steps of k16
            uint32_t af[4][4], bf[8][2];
#pragma unroll
            for (int mt = 0; mt < 4; mt++)
                ldm4(af[mt], ab + (uint32_t)(mt * 16 * 144 + ks * 32));
#pragma unroll
            for (int p = 0; p < 4; p++) {
                uint32_t r4[4];
                ldm4(r4, bb + (uint32_t)(p * 16 * 144 + ks * 32));
                bf[2 * p][0] = r4[0]; bf[2 * p][1] = r4[1];
                bf[2 * p + 1][0] = r4[2]; bf[2 * p + 1][1] = r4[3];
            }
#pragma unroll
            for (int mt = 0; mt < 4; mt++)
#pragma unroll
                for (int nt = 0; nt < 8; nt++)
                    mma16(acc[mt][nt], af[mt], bf[nt]);
        }
        __syncthreads();
        if (kc + 2 < KT) load(kc + 2, s);
        else             CP_COMMIT();
    }

    // epilogue: c0=(g,2t) c1=(g,2t+1) c2=(g+8,2t) c3=(g+8,2t+1)
#pragma unroll
    for (int mt = 0; mt < 4; mt++) {
#pragma unroll
        for (int half = 0; half < 2; half++) {
            const int r = m0 + wm + mt * 16 + q + half * 8;
#pragma unroll
            for (int nt = 0; nt < 8; nt++) {
                int n = n0 + wn + nt * 8 + 2 * t;
                float vx = acc[mt][nt][half * 2 + 0];
                float vy = acc[mt][nt][half * 2 + 1];
                if (BIAS) { float2 b = *(const float2*)&bias[n]; vx += b.x; vy += b.y; }
                if (RES)  { const float2 rr = *(const float2*)&res[(size_t)r * N + n]; vx += rr.x; vy += rr.y; }
                if (HALF_OUT)
                    *(__half2*)((__half*)Cv + (size_t)r * N + n) = __floats2half2_rn(vx, vy);
                else
                    *(float2*)((float*)Cv + (size_t)r * N + n) = make_float2(vx, vy);
            }
        }
    }
}

// ---------------- fp16 dual GEMM: C = silu(A@B1^T) * (A@B2^T), fp16 out ----
// CTA 128x64, BK=64, 4 warps (2x2), warp tile 64x32 per matrix.
// N loop bound = NPAD (B rows >= NREAL are zero-filled -> C pad written zero).
__global__ void __launch_bounds__(128, 2) gemm_dual_h(
    const __half* __restrict__ A, const __half* __restrict__ B1,
    const __half* __restrict__ B2, __half* __restrict__ C,
    int NPAD, int NREAL, int K)
{
    extern __shared__ __half sh[];
    const int tid = threadIdx.x, wid = tid >> 5, lane = tid & 31;
    const int q = lane >> 2, t = lane & 3;
    const int m0 = blockIdx.y * 128, n0 = blockIdx.x * 64;
    const int wm = (wid >> 1) * 64, wn = (wid & 1) * 32;
    const int KT = K >> 6;
    const uint32_t sbase = smem_u32(sh);

    auto load = [&](int kc_, int s) {
        const int k0 = kc_ << 6;
        const uint32_t as  = sbase + s * 36864u;
        const uint32_t b1s = as + 18432u;
        const uint32_t b2s = as + 27648u;
#pragma unroll
        for (int i = 0; i < 8; i++) {           // A: 128 rows
            int idx = tid + i * 128;
            int r = idx >> 3, c = idx & 7;
            cp16(as + (uint32_t)(r * 144 + c * 16),
                 A + (size_t)(m0 + r) * K + k0 + c * 8, 16u);
        }
#pragma unroll
        for (int i = 0; i < 4; i++) {           // B1+B2: 64 rows each
            int idx = tid + i * 128;
            int r = idx >> 3, c = idx & 7;
            uint32_t ok = (n0 + r < NREAL) ? 16u : 0u;
            size_t off = (size_t)(ok ? (n0 + r) : 0) * K + k0 + c * 8;
            uint32_t sw = (uint32_t)(r * 144 + c * 16);
            cp16(b1s + sw, B1 + off, ok);
            cp16(b2s + sw, B2 + off, ok);
        }
        CP_COMMIT();
    };

    float acc1[4][4][4] = {};
    float acc2[4][4][4] = {};
    load(0, 0);
    load(1, 1);

    const uint32_t a_lane_off = (uint32_t)((lane & 15) * 144 + ((lane >> 4) << 4));
    const uint32_t b_lane_off = (uint32_t)(((lane & 7) + ((lane >> 4) << 3)) * 144
                                           + (((lane >> 3) & 1) << 4));

    for (int kc = 0; kc < KT; kc++) {
        const int s = kc & 1;
        CP_WAIT1();
        __syncthreads();
        const uint32_t as  = sbase + s * 36864u;
        const uint32_t ab  = as + (uint32_t)(wm * 144) + a_lane_off;
        const uint32_t b1b = as + 18432u + (uint32_t)(wn * 144) + b_lane_off;
        const uint32_t b2b = as + 27648u + (uint32_t)(wn * 144) + b_lane_off;
#pragma unroll
        for (int ks = 0; ks < 4; ks++) {
            uint32_t af[4][4], b1f[4][2], b2f[4][2];
#pragma unroll
            for (int mt = 0; mt < 4; mt++)
                ldm4(af[mt], ab + (uint32_t)(mt * 16 * 144 + ks * 32));
#pragma unroll
            for (int p = 0; p < 2; p++) {
                uint32_t r4[4];
                ldm4(r4, b1b + (uint32_t)(p * 16 * 144 + ks * 32));
                b1f[2 * p][0] = r4[0]; b1f[2 * p][1] = r4[1];
                b1f[2 * p + 1][0] = r4[2]; b1f[2 * p + 1][1] = r4[3];
                ldm4(r4, b2b + (uint32_t)(p * 16 * 144 + ks * 32));
                b2f[2 * p][0] = r4[0]; b2f[2 * p][1] = r4[1];
                b2f[2 * p + 1][0] = r4[2]; b2f[2 * p + 1][1] = r4[3];
            }
#pragma unroll
            for (int mt = 0; mt < 4; mt++)
#pragma unroll
                for (int nt = 0; nt < 4; nt++) {
                    mma16(acc1[mt][nt], af[mt], b1f[nt]);
                    mma16(acc2[mt][nt], af[mt], b2f[nt]);
                }
        }
        __syncthreads();
        if (kc + 2 < KT) load(kc + 2, s);
        else             CP_COMMIT();
    }

    // epilogue: silu(acc1) * acc2 -> fp16 (pads come out zero)
#pragma unroll
    for (int mt = 0; mt < 4; mt++) {
#pragma unroll
        for (int half = 0; half < 2; half++) {
            const int r = m0 + wm + mt * 16 + q + half * 8;
            __half* Crow = C + (size_t)r * NPAD;
#pragma unroll
            for (int nt = 0; nt < 4; nt++) {
                int n = n0 + wn + nt * 8 + 2 * t;
                float u0 = acc1[mt][nt][half * 2 + 0];
                float u1 = acc1[mt][nt][half * 2 + 1];
                float o0 = u0 / (1.f + expf(-u0)) * acc2[mt][nt][half * 2 + 0];
                float o1 = u1 / (1.f + expf(-u1)) * acc2[mt][nt][half * 2 + 1];
                *(__half2*)&Crow[n] = __floats2half2_rn(o0, o1);
            }
        }
    }
}

// ---------------- launch ---------------------------------------------------
extern "C" void kernel_launch(void* const* d_in, const int* in_sizes, int n_in,
                              void* d_out, int out_size)
{
    const float* x          = (const float*)d_in[0];
    const float* state      = (const float*)d_in[1];
    const float* g1         = (const float*)d_in[2];
    const float* g2         = (const float*)d_in[3];
    const float* in_proj_w  = (const float*)d_in[4];
    const float* in_proj_b  = (const float*)d_in[5];
    const float* out_proj_w = (const float*)d_in[6];
    const float* out_proj_b = (const float*)d_in[7];
    const float* w1         = (const float*)d_in[8];
    const float* w2         = (const float*)d_in[9];
    const float* w3         = (const float*)d_in[10];
    float* out = (float*)d_out;

    const float* wv = in_proj_w + (size_t)2 * DIM * DIM;   // only V slice live
    const float* bv = in_proj_b + 2 * DIM;

    float *h1, *h2;  __half *hn1, *vh, *hn2, *ffh, *wvh, *owh, *w1h, *w2h, *w3h;
    cudaGetSymbolAddress((void**)&h1,  g_h1);
    cudaGetSymbolAddress((void**)&h2,  g_h2);
    cudaGetSymbolAddress((void**)&hn1, g_hn1);
    cudaGetSymbolAddress((void**)&vh,  g_vh);
    cudaGetSymbolAddress((void**)&hn2, g_hn2);
    cudaGetSymbolAddress((void**)&ffh, g_ffh);
    cudaGetSymbolAddress((void**)&wvh, g_wvh);
    cudaGetSymbolAddress((void**)&owh, g_owh);
    cudaGetSymbolAddress((void**)&w1h, g_w1h);
    cudaGetSymbolAddress((void**)&w2h, g_w2h);
    cudaGetSymbolAddress((void**)&w3h, g_w3h);

    const int SMEM = 73728;
    cudaFuncSetAttribute(gemm_h<true,  false, true >, cudaFuncAttributeMaxDynamicSharedMemorySize, SMEM);
    cudaFuncSetAttribute(gemm_h<true,  true,  false>, cudaFuncAttributeMaxDynamicSharedMemorySize, SMEM);
    cudaFuncSetAttribute(gemm_h<false, true,  false>, cudaFuncAttributeMaxDynamicSharedMemorySize, SMEM);
    cudaFuncSetAttribute(gemm_dual_h,                 cudaFuncAttributeMaxDynamicSharedMemorySize, SMEM);

    // 0. weight conversions (part of the graph; ~40us)
    {
        int n4;
        n4 = DIM * DIM / 4;
        f2h_kernel<<<(n4 + 255) / 256, 256>>>(wv, wvh, n4);
        f2h_kernel<<<(n4 + 255) / 256, 256>>>(out_proj_w, owh, n4);
        n4 = HIDDEN * DIM / 4;
        f2h_kernel<<<(n4 + 255) / 256, 256>>>(w1, w1h, n4);
        f2h_kernel<<<(n4 + 255) / 256, 256>>>(w2, w2h, n4);
        int tot = DIM * HPAD;
        f2h_pad_kernel<<<(tot + 255) / 256, 256>>>(w3, w3h, DIM, HIDDEN, HPAD);
    }

    // 1. h1 = x + state ; hn1 = rmsnorm(h1, g1) -> fp16
    rmsnorm_kernel<true><<<BATCH, 256>>>(x, state, g1, h1, hn1);

    // 2. v = hn1 @ wv^T + bv -> fp16
    gemm_h<true, false, true><<<dim3(DIM / 128, BATCH / 128), 128, SMEM>>>(
        hn1, wvh, bv, nullptr, vh, DIM, DIM);

    // 3. h2 = h1 + v @ out_proj_w^T + out_proj_b -> fp32
    gemm_h<true, true, false><<<dim3(DIM / 128, BATCH / 128), 128, SMEM>>>(
        vh, owh, out_proj_b, h1, h2, DIM, DIM);

    // 4. hn2 = rmsnorm(h2, g2) -> fp16
    rmsnorm_kernel<false><<<BATCH, 256>>>(h2, nullptr, g2, nullptr, hn2);

    // 5. ffh = silu(hn2 @ w1^T) * (hn2 @ w2^T) -> fp16 (padded to HPAD)
    gemm_dual_h<<<dim3(HPAD / 64, BATCH / 128), 128, SMEM>>>(
        hn2, w1h, w2h, ffh, HPAD, HIDDEN, DIM);

    // 6. out = h2 + ffh @ w3^T -> fp32 (K = HPAD, zero-padded)
    gemm_h<false, true, false><<<dim3(DIM / 128, BATCH / 128), 128, SMEM>>>(
        ffh, w3h, nullptr, h2, out, DIM, HPAD);
}